// round 14
// baseline (speedup 1.0000x reference)
#include <cuda_runtime.h>
#include <cuda_bf16.h>
#include <cstdint>

// ---------------- problem constants ----------------
constexpr int T_ = 64, N_ = 40, D_ = 4, H_ = 256, R_ = 64;
constexpr int E_ = N_ * (N_ - 1);        // 1560
constexpr int TE = T_ * E_;              // 99840
constexpr int TN = T_ * N_;              // 2560

// ---------------- scratch ----------------
__device__ __align__(16) __nv_bfloat16 g_nbh[TN * H_], g_nbl[TN * H_];
__device__ __align__(16) __nv_bfloat16 g_h1h[TN * H_], g_h1l[TN * H_];
__device__ __align__(16) __nv_bfloat16 g_nsh[TN * H_], g_nsl[TN * H_];
__device__ __align__(16) __nv_bfloat16 g_n3h[TN * H_], g_n3l[TN * H_];
__device__ __align__(16) __nv_bfloat16 g_tmph[TE * H_], g_tmpl[TE * H_];
__device__ __align__(16) __nv_bfloat16 g_e2h[TE * H_], g_e2l[TE * H_];
__device__ __align__(16) __nv_bfloat16 g_e4h[TE * H_], g_e4l[TE * H_];
__device__ __align__(16) float g_P[TN * 512];
__device__ __align__(16) float g_Q[TN * 512];
__device__ __align__(16) float g_g[(size_t)TE * 512];
constexpr int NSEG = 12;
constexpr int SEGSZ = 65536;
__device__ __align__(16) __nv_bfloat16 g_whi[NSEG * SEGSZ], g_wlo[NSEG * SEGSZ];
__device__ float g_hf[TE * R_];
__device__ float g_hr[TE * R_];
__device__ int   g_rlist[N_ * (N_ - 1)];

__device__ __forceinline__ float eluf(float v) { return v > 0.f ? v : expm1f(v); }
__device__ __forceinline__ float sigmf(float v) { return 1.f / (1.f + expf(-v)); }

__device__ __forceinline__ void bsplit2(float x0, float x1, uint32_t& hi, uint32_t& lo) {
    asm("cvt.rn.bf16x2.f32 %0, %1, %2;" : "=r"(hi) : "f"(x1), "f"(x0));
    __nv_bfloat162 h = *reinterpret_cast<__nv_bfloat162*>(&hi);
    float r0 = x0 - __bfloat162float(h.x);
    float r1 = x1 - __bfloat162float(h.y);
    asm("cvt.rn.bf16x2.f32 %0, %1, %2;" : "=r"(lo) : "f"(r1), "f"(r0));
}

// scalar-operand mma: no staging arrays -> no register MOVs
__device__ __forceinline__ void mma_bf16(float* d, const uint32_t* a, uint32_t b0, uint32_t b1) {
    asm volatile(
        "mma.sync.aligned.m16n8k16.row.col.f32.bf16.bf16.f32 "
        "{%0,%1,%2,%3},{%4,%5,%6,%7},{%8,%9},{%0,%1,%2,%3};"
        : "+f"(d[0]), "+f"(d[1]), "+f"(d[2]), "+f"(d[3])
        : "r"(a[0]), "r"(a[1]), "r"(a[2]), "r"(a[3]), "r"(b0), "r"(b1));
}

__device__ __forceinline__ void ldsm4(uint32_t* r, uint32_t addr) {
    asm volatile("ldmatrix.sync.aligned.m8n8.x4.shared.b16 {%0,%1,%2,%3}, [%4];"
                 : "=r"(r[0]), "=r"(r[1]), "=r"(r[2]), "=r"(r[3]) : "r"(addr));
}

__device__ __forceinline__ uint32_t smem_u32(const void* p) {
    uint32_t a;
    asm("{ .reg .u64 t; cvta.to.shared.u64 t, %1; cvt.u32.u64 %0, t; }" : "=r"(a) : "l"(p));
    return a;
}

// packed fp32x2 helpers
#define PACKF2(d, lo, hi) asm("mov.b64 %0, {%1, %2};" : "=l"(d) : "f"(lo), "f"(hi))
#define UNPACKF2(lo, hi, s) asm("mov.b64 {%0, %1}, %2;" : "=f"(lo), "=f"(hi) : "l"(s))
#define FMA2(d, a, b) asm("fma.rn.f32x2 %0, %1, %2, %0;" : "+l"(d) : "l"(a), "l"(b))

// ---------------- fused prep: weight split + mlp1 fc1 + rlist ----------------
struct SplitSeg { const float* src; int stride; int coff; };
struct SplitArgs { SplitSeg s[NSEG]; };
constexpr int PREP_SPLIT_BLKS = NSEG * 256;
constexpr int PREP_MLP1_BLKS = TN * H_ / 256;
constexpr int PREP_GRID = PREP_SPLIT_BLKS + PREP_MLP1_BLKS + 1;

__global__ void prep(SplitArgs a, __nv_bfloat16* __restrict__ oh,
                     __nv_bfloat16* __restrict__ ol,
                     const float* __restrict__ x, const float* __restrict__ W1,
                     const float* __restrict__ b1, const int* __restrict__ recv) {
    int id = blockIdx.x;
    int tid = threadIdx.x;
    if (id < PREP_SPLIT_BLKS) {
        int seg = id >> 8;
        int idx = (id & 255) * 256 + tid;
        int j = idx >> 8, k = idx & 255;
        const SplitSeg s = a.s[seg];
        float v = s.src[j * s.stride + s.coff + k];
        __nv_bfloat16 h = __float2bfloat16(v);
        int o = seg * SEGSZ + idx;
        oh[o] = h;
        ol[o] = __float2bfloat16(v - __bfloat162float(h));
    } else if (id < PREP_SPLIT_BLKS + PREP_MLP1_BLKS) {
        int idx = (id - PREP_SPLIT_BLKS) * 256 + tid;
        int row = idx >> 8;
        int j = idx & 255;
        const float* xr = x + row * D_;
        const float* w = W1 + j * D_;
        float v = b1[j] + xr[0] * w[0] + xr[1] * w[1] + xr[2] * w[2] + xr[3] * w[3];
        v = eluf(v);
        __nv_bfloat16 h = __float2bfloat16(v);
        g_nbh[idx] = h;
        g_nbl[idx] = __float2bfloat16(v - __bfloat162float(h));
    } else {
        int n = tid;
        if (n < N_) {
            int p = 0;
            for (int e = 0; e < E_; e++)
                if (recv[e] == n) g_rlist[n * (N_ - 1) + p++] = e;
        }
    }
}

// ---------------- edge2node scatter-add ----------------
__global__ void edge2node() {
    int b = blockIdx.x;
    int t = b / N_;
    int n = b - t * N_;
    int c = threadIdx.x;
    const int* lst = g_rlist + n * (N_ - 1);
    float s = 0.f;
#pragma unroll 13
    for (int i = 0; i < N_ - 1; i++) {
        int e = lst[i];
        size_t idx = ((size_t)t * E_ + e) * H_ + c;
        s += __bfloat162float(g_e2h[idx]) + __bfloat162float(g_e2l[idx]);
    }
    __nv_bfloat16 h = __float2bfloat16(s);
    g_nsh[(size_t)b * H_ + c] = h;
    g_nsl[(size_t)b * H_ + c] = __float2bfloat16(s - __bfloat162float(h));
}

// ------- bf16x3 tensor-core GEMM: 128x256 block, 512 threads, LDSM, K=256 -------
// Pass-major MMA ordering: same acc touched at distance 16 (RAW covered).
// EPI 0: fp32 out; if b0p non-null, +b0p[cg] for cg<256 only.
// EPI 1: +b0, ELU, split bf16 out. EPI 2: +b0 + Q gather, ELU, split bf16 out.
// EPI 3: fp32 out, cg<256 ? b0+b1 : b2+b3.
// LOADP: A rows = elu(P[send]+P[recv]) on the fly.
template <int EPI, bool LOADP>
__global__ __launch_bounds__(512, 1) void gemm_tc(
    const __nv_bfloat16* __restrict__ Ah, const __nv_bfloat16* __restrict__ Al,
    const __nv_bfloat16* __restrict__ Wh, const __nv_bfloat16* __restrict__ Wl,
    const float* __restrict__ b0p, const float* __restrict__ b1p,
    const float* __restrict__ b2p, const float* __restrict__ b3p,
    float* __restrict__ Cf, __nv_bfloat16* __restrict__ Ch, __nv_bfloat16* __restrict__ Cl,
    int ldc,
    const int* __restrict__ send, const int* __restrict__ recv,
    const float* __restrict__ Q) {
    __shared__ __align__(16) char smem[36864];
    const uint32_t sb = smem_u32(smem);
    const int tid = threadIdx.x;
    const int bm = blockIdx.y * 128;
    const int bn = blockIdx.x * 256;
    const int warp = tid >> 5, lane = tid & 31;

    const bool do_a = tid < 256;
    const int arow = (tid & 255) >> 1;
    const int ahalf = tid & 1;
    const __nv_bfloat16* arh = Ah + (size_t)(bm + arow) * H_ + ahalf * 8;
    const __nv_bfloat16* arl = Al + (size_t)(bm + arow) * H_ + ahalf * 8;
    const float *p0 = nullptr, *p1 = nullptr;
    if (LOADP && do_a) {
        int m = bm + arow;
        int t = m / E_;
        int e = m - t * E_;
        p0 = Q + ((size_t)t * N_ + send[e]) * 512 + ahalf * 8;
        p1 = Q + ((size_t)t * N_ + recv[e]) * 512 + 256 + ahalf * 8;
    }
    const int brow = tid >> 1;
    const int bhalf = tid & 1;
    const __nv_bfloat16* wrh = Wh + (size_t)(bn + brow) * H_ + bhalf * 8;
    const __nv_bfloat16* wrl = Wl + (size_t)(bn + brow) * H_ + bhalf * 8;
    char* a_sts = smem + arow * 48 + ahalf * 16;
    char* b_sts = smem + 12288 + brow * 48 + bhalf * 16;

    const int wm = (warp >> 3) * 64;
    const int wn = (warp & 7) * 32;
    const int lrow = lane & 15, lkh = lane >> 4;
    const uint32_t abase = sb + (uint32_t)((wm + lrow) * 48 + lkh * 16);
    const uint32_t bbase = sb + 12288u + (uint32_t)((wn + lrow) * 48 + lkh * 16);

    float acc[4][4][4] = {};

    uint4 vah, vaL, vwh, vwL;
    auto load_g = [&](int kt) {
        if (do_a) {
            if (LOADP) {
                float4 x0 = *(const float4*)(p0 + kt);
                float4 x1 = *(const float4*)(p0 + kt + 4);
                float4 y0 = *(const float4*)(p1 + kt);
                float4 y1 = *(const float4*)(p1 + kt + 4);
                float v0 = eluf(x0.x + y0.x), v1 = eluf(x0.y + y0.y);
                float v2 = eluf(x0.z + y0.z), v3 = eluf(x0.w + y0.w);
                float v4 = eluf(x1.x + y1.x), v5 = eluf(x1.y + y1.y);
                float v6 = eluf(x1.z + y1.z), v7 = eluf(x1.w + y1.w);
                bsplit2(v0, v1, vah.x, vaL.x);
                bsplit2(v2, v3, vah.y, vaL.y);
                bsplit2(v4, v5, vah.z, vaL.z);
                bsplit2(v6, v7, vah.w, vaL.w);
            } else {
                vah = *(const uint4*)(arh + kt);
                vaL = *(const uint4*)(arl + kt);
            }
        }
        vwh = *(const uint4*)(wrh + kt);
        vwL = *(const uint4*)(wrl + kt);
    };
    load_g(0);

#pragma unroll 1
    for (int step = 0; step < 16; step++) {
        __syncthreads();
        if (do_a) {
            *(uint4*)(a_sts + 0)    = vah;
            *(uint4*)(a_sts + 6144) = vaL;
        }
        *(uint4*)(b_sts + 0)     = vwh;
        *(uint4*)(b_sts + 12288) = vwL;
        __syncthreads();
        if (step < 15) load_g((step + 1) * 16);

        uint32_t ah[4][4], al[4][4], bh[2][4], bl[2][4];
#pragma unroll
        for (int mf = 0; mf < 4; mf++) {
            ldsm4(ah[mf], abase + mf * 768u);
            ldsm4(al[mf], abase + mf * 768u + 6144u);
        }
#pragma unroll
        for (int p = 0; p < 2; p++) {
            ldsm4(bh[p], bbase + p * 768u);
            ldsm4(bl[p], bbase + p * 768u + 12288u);
        }
        // pass-major: all hh, then all hl, then all lh — acc RAW distance 16
#pragma unroll
        for (int nf = 0; nf < 4; nf++) {
            const int p = nf >> 1, o = nf & 1;
#pragma unroll
            for (int mf = 0; mf < 4; mf++)
                mma_bf16(acc[mf][nf], ah[mf], bh[p][o], bh[p][o + 2]);
        }
#pragma unroll
        for (int nf = 0; nf < 4; nf++) {
            const int p = nf >> 1, o = nf & 1;
#pragma unroll
            for (int mf = 0; mf < 4; mf++)
                mma_bf16(acc[mf][nf], ah[mf], bl[p][o], bl[p][o + 2]);
        }
#pragma unroll
        for (int nf = 0; nf < 4; nf++) {
            const int p = nf >> 1, o = nf & 1;
#pragma unroll
            for (int mf = 0; mf < 4; mf++)
                mma_bf16(acc[mf][nf], al[mf], bh[p][o], bh[p][o + 2]);
        }
    }

    // ---- epilogue ----
    const int grp = lane >> 2, q = lane & 3;
#pragma unroll
    for (int mf = 0; mf < 4; mf++) {
        int r0 = bm + wm + mf * 16 + grp;
        int r1 = r0 + 8;
        size_t qs0 = 0, qr0 = 0, qs1 = 0, qr1 = 0;
        if (EPI == 2) {
            int t0 = r0 / E_, e0 = r0 - t0 * E_;
            int t1 = r1 / E_, e1 = r1 - t1 * E_;
            qs0 = ((size_t)t0 * N_ + send[e0]) * 512;
            qr0 = ((size_t)t0 * N_ + recv[e0]) * 512 + 256;
            qs1 = ((size_t)t1 * N_ + send[e1]) * 512;
            qr1 = ((size_t)t1 * N_ + recv[e1]) * 512 + 256;
        }
#pragma unroll
        for (int nf = 0; nf < 4; nf++) {
            int col = wn + nf * 8 + 2 * q;
            int cg = bn + col;
            float b0 = 0.f, b1 = 0.f;
            if (EPI == 1 || EPI == 2) { b0 = b0p[col]; b1 = b0p[col + 1]; }
            if (EPI == 0 && b0p != nullptr && cg < 256) { b0 = b0p[cg]; b1 = b0p[cg + 1]; }
            if (EPI == 3) {
                if (cg < 256) { b0 = b0p[cg] + b1p[cg]; b1 = b0p[cg + 1] + b1p[cg + 1]; }
                else { b0 = b2p[cg - 256] + b3p[cg - 256]; b1 = b2p[cg - 255] + b3p[cg - 255]; }
            }
            float x0 = acc[mf][nf][0] + b0;
            float x1 = acc[mf][nf][1] + b1;
            float x2 = acc[mf][nf][2] + b0;
            float x3 = acc[mf][nf][3] + b1;
            if (EPI == 2) {
                x0 += Q[qs0 + col] + Q[qr0 + col];
                x1 += Q[qs0 + col + 1] + Q[qr0 + col + 1];
                x2 += Q[qs1 + col] + Q[qr1 + col];
                x3 += Q[qs1 + col + 1] + Q[qr1 + col + 1];
            }
            if (EPI == 1 || EPI == 2) {
                x0 = eluf(x0); x1 = eluf(x1); x2 = eluf(x2); x3 = eluf(x3);
                uint32_t h01, l01, h23, l23;
                bsplit2(x0, x1, h01, l01);
                bsplit2(x2, x3, h23, l23);
                *(uint32_t*)(Ch + (size_t)r0 * 256 + col) = h01;
                *(uint32_t*)(Cl + (size_t)r0 * 256 + col) = l01;
                *(uint32_t*)(Ch + (size_t)r1 * 256 + col) = h23;
                *(uint32_t*)(Cl + (size_t)r1 * 256 + col) = l23;
            } else {
                *(float2*)(Cf + (size_t)r0 * ldc + cg) = make_float2(x0, x1);
                *(float2*)(Cf + (size_t)r1 * ldc + cg) = make_float2(x2, x3);
            }
        }
    }
}

// ---- bidirectional LSTM: 256-thread blocks, 4 edge-groups share Whh, fp32x2 packed FMA ----
constexpr int LSTM_GROUPS = E_ / 8;
constexpr int LSTM_GPB = 4;
constexpr int LSTM_BPD = (LSTM_GROUPS + LSTM_GPB - 1) / LSTM_GPB;
constexpr int LSTM_SMEM = 64 * 256 * 4 + LSTM_GPB * 64 * 8 * 4;

__global__ __launch_bounds__(256) void lstm_kernel(
    const float* __restrict__ gates,
    const float* __restrict__ fWhh, const float* __restrict__ rWhh,
    float* __restrict__ hfOut, float* __restrict__ hrOut) {
    extern __shared__ float sm[];
    float* Wq = sm;
    float4* hsm = (float4*)(sm + 64 * 256);

    const int bid = blockIdx.x;
    const int dir = (bid >= LSTM_BPD) ? 1 : 0;
    const int bg = dir ? (bid - LSTM_BPD) : bid;
    const float* Whh = dir ? rWhh : fWhh;
    float* hout = dir ? hrOut : hfOut;
    const int doff = dir * 256;
    const int tid = threadIdx.x;
    const int sub = tid >> 6, j = tid & 63;
    const int grp = bg * LSTM_GPB + sub;
    const bool valid = grp < LSTM_GROUPS;
    const int e0 = (valid ? grp : LSTM_GROUPS - 1) * 8;

    for (int idx = tid; idx < 64 * 256; idx += 256) {
        int k = idx >> 8;
        int rem = idx & 255;
        int jj = rem >> 2;
        int q = rem & 3;
        Wq[idx] = Whh[(q * 64 + jj) * 64 + k];
    }
    float4* hme = hsm + sub * 128;
    for (int i = j; i < 128; i += 64) hme[i] = make_float4(0.f, 0.f, 0.f, 0.f);

    float c[8];
#pragma unroll
    for (int e = 0; e < 8; e++) c[e] = 0.f;
    __syncthreads();

    for (int s = 0; s < T_; s++) {
        int t = dir ? (T_ - 1 - s) : s;
        unsigned long long A0[4], A1[4], A2[4], A3[4];
        {
            float a0[8], a1[8], a2[8], a3[8];
#pragma unroll
            for (int e = 0; e < 8; e++) {
                const float* gp = gates + ((size_t)t * E_ + e0 + e) * 512 + doff;
                a0[e] = gp[j]; a1[e] = gp[64 + j]; a2[e] = gp[128 + j]; a3[e] = gp[192 + j];
            }
#pragma unroll
            for (int p = 0; p < 4; p++) {
                PACKF2(A0[p], a0[2 * p], a0[2 * p + 1]);
                PACKF2(A1[p], a1[2 * p], a1[2 * p + 1]);
                PACKF2(A2[p], a2[2 * p], a2[2 * p + 1]);
                PACKF2(A3[p], a3[2 * p], a3[2 * p + 1]);
            }
        }
#pragma unroll 8
        for (int k = 0; k < 64; k++) {
            float4 w = *(const float4*)&Wq[k * 256 + j * 4];
            unsigned long long wx, wy, wz, ww;
            PACKF2(wx, w.x, w.x);
            PACKF2(wy, w.y, w.y);
            PACKF2(wz, w.z, w.z);
            PACKF2(ww, w.w, w.w);
            const ulonglong2* hp = (const ulonglong2*)(hme + k * 2);
            ulonglong2 hA = hp[0], hB = hp[1];
            unsigned long long hv[4] = {hA.x, hA.y, hB.x, hB.y};
#pragma unroll
            for (int p = 0; p < 4; p++) {
                FMA2(A0[p], hv[p], wx);
                FMA2(A1[p], hv[p], wy);
                FMA2(A2[p], hv[p], wz);
                FMA2(A3[p], hv[p], ww);
            }
        }
        __syncthreads();
        float a0[8], a1[8], a2[8], a3[8];
#pragma unroll
        for (int p = 0; p < 4; p++) {
            UNPACKF2(a0[2 * p], a0[2 * p + 1], A0[p]);
            UNPACKF2(a1[2 * p], a1[2 * p + 1], A1[p]);
            UNPACKF2(a2[2 * p], a2[2 * p + 1], A2[p]);
            UNPACKF2(a3[2 * p], a3[2 * p + 1], A3[p]);
        }
        float hn[8];
#pragma unroll
        for (int e = 0; e < 8; e++) {
            float iv = sigmf(a0[e]);
            float fv = sigmf(a1[e]);
            float gv = tanhf(a2[e]);
            float ov = sigmf(a3[e]);
            c[e] = fv * c[e] + iv * gv;
            hn[e] = ov * tanhf(c[e]);
        }
        hme[j * 2 + 0] = make_float4(hn[0], hn[1], hn[2], hn[3]);
        hme[j * 2 + 1] = make_float4(hn[4], hn[5], hn[6], hn[7]);
        if (valid) {
#pragma unroll
            for (int e = 0; e < 8; e++)
                hout[((size_t)t * E_ + e0 + e) * 64 + j] = hn[e];
        }
        __syncthreads();
    }
}

// ---------------- output projection ----------------
__global__ void out_proj(const float* __restrict__ hf, const float* __restrict__ hr,
                         const float* __restrict__ priW, const float* __restrict__ prib,
                         const float* __restrict__ encW, const float* __restrict__ encb,
                         float* __restrict__ out) {
    int m = blockIdx.x * blockDim.x + threadIdx.x;
    if (m >= TE) return;
    const float* f = hf + (size_t)m * 64;
    const float* r = hr + (size_t)m * 64;
    float p0 = prib[0], p1 = prib[1], e0 = encb[0], e1 = encb[1];
#pragma unroll 8
    for (int k = 0; k < 64; k++) {
        float fv = f[k];
        p0 = fmaf(fv, priW[k], p0);
        p1 = fmaf(fv, priW[64 + k], p1);
        e0 = fmaf(fv, encW[k], e0);
        e1 = fmaf(fv, encW[128 + k], e1);
    }
#pragma unroll 8
    for (int k = 0; k < 64; k++) {
        float rv = r[k];
        e0 = fmaf(rv, encW[64 + k], e0);
        e1 = fmaf(rv, encW[192 + k], e1);
    }
    float4 o = make_float4(p0, p1, e0, e1);
    *(float4*)(out + (size_t)m * 4) = o;
}

// ---------------- host launch ----------------
extern "C" void kernel_launch(void* const* d_in, const int* in_sizes, int n_in,
                              void* d_out, int out_size) {
    const float* x     = (const float*)d_in[0];
    const int* send    = (const int*)d_in[2];
    const int* recv    = (const int*)d_in[3];
    const float* m1W1 = (const float*)d_in[4],  *m1b1 = (const float*)d_in[5];
    const float* m1W2 = (const float*)d_in[6],  *m1b2 = (const float*)d_in[7];
    const float* m2W1 = (const float*)d_in[8],  *m2b1 = (const float*)d_in[9];
    const float* m2W2 = (const float*)d_in[10], *m2b2 = (const float*)d_in[11];
    const float* m3W1 = (const float*)d_in[12], *m3b1 = (const float*)d_in[13];
    const float* m3W2 = (const float*)d_in[14], *m3b2 = (const float*)d_in[15];
    const float* m4W1 = (const float*)d_in[16], *m4b1 = (const float*)d_in[17];
    const float* m4W2 = (const float*)d_in[18], *m4b2 = (const float*)d_in[19];
    const float* fWih = (const float*)d_in[20], *fWhh = (const float*)d_in[21];
    const float* fbih = (const float*)d_in[22], *fbhh = (const float*)d_in[23];
    const float* rWih = (const float*)d_in[24], *rWhh = (const float*)d_in[25];
    const float* rbih = (const float*)d_in[26], *rbhh = (const float*)d_in[27];
    const float* encW = (const float*)d_in[28], *encb = (const float*)d_in[29];
    const float* priW = (const float*)d_in[30], *prib = (const float*)d_in[31];

    __nv_bfloat16 *whi, *wlo, *nbh, *nbl, *h1h, *h1l, *nsh, *nsl, *n3h, *n3l;
    __nv_bfloat16 *tmph, *tmpl, *e2h, *e2l, *e4h, *e4l;
    float *P, *Q, *gg, *hfp, *hrp;
    cudaGetSymbolAddress((void**)&whi,  g_whi);
    cudaGetSymbolAddress((void**)&wlo,  g_wlo);
    cudaGetSymbolAddress((void**)&nbh,  g_nbh);
    cudaGetSymbolAddress((void**)&nbl,  g_nbl);
    cudaGetSymbolAddress((void**)&h1h,  g_h1h);
    cudaGetSymbolAddress((void**)&h1l,  g_h1l);
    cudaGetSymbolAddress((void**)&nsh,  g_nsh);
    cudaGetSymbolAddress((void**)&nsl,  g_nsl);
    cudaGetSymbolAddress((void**)&n3h,  g_n3h);
    cudaGetSymbolAddress((void**)&n3l,  g_n3l);
    cudaGetSymbolAddress((void**)&tmph, g_tmph);
    cudaGetSymbolAddress((void**)&tmpl, g_tmpl);
    cudaGetSymbolAddress((void**)&e2h,  g_e2h);
    cudaGetSymbolAddress((void**)&e2l,  g_e2l);
    cudaGetSymbolAddress((void**)&e4h,  g_e4h);
    cudaGetSymbolAddress((void**)&e4l,  g_e4l);
    cudaGetSymbolAddress((void**)&P,    g_P);
    cudaGetSymbolAddress((void**)&Q,    g_Q);
    cudaGetSymbolAddress((void**)&gg,   g_g);
    cudaGetSymbolAddress((void**)&hfp,  g_hf);
    cudaGetSymbolAddress((void**)&hrp,  g_hr);

    cudaFuncSetAttribute(lstm_kernel, cudaFuncAttributeMaxDynamicSharedMemorySize, LSTM_SMEM);

    SplitArgs sa;
    sa.s[0]  = {m1W2, 256, 0};
    sa.s[1]  = {m2W1, 512, 0};
    sa.s[2]  = {m2W1, 512, 256};
    sa.s[3]  = {m2W2, 256, 0};
    sa.s[4]  = {m3W1, 256, 0};
    sa.s[5]  = {m3W2, 256, 0};
    sa.s[6]  = {m4W1, 768, 0};
    sa.s[7]  = {m4W1, 768, 256};
    sa.s[8]  = {m4W1, 768, 512};
    sa.s[9]  = {m4W2, 256, 0};
    sa.s[10] = {fWih, 256, 0};
    sa.s[11] = {rWih, 256, 0};

    const dim3 gN(1, TN / 128);
    const dim3 gN2(2, TN / 128);
    const dim3 gE(1, TE / 128);
    const dim3 gE2(2, TE / 128);

    // 1: prep
    prep<<<PREP_GRID, 256>>>(sa, whi, wlo, x, m1W1, m1b1, recv);
    // 2: mlp1 fc2 (node)
    gemm_tc<1, false><<<gN, 512>>>(nbh, nbl, whi + 0 * SEGSZ, wlo + 0 * SEGSZ,
        m1b2, nullptr, nullptr, nullptr, nullptr, h1h, h1l, 256, nullptr, nullptr, nullptr);
    // 3: mlp2 fc1 node products P = h1 @ [Ws|Wr]  (+ m2b1 on first half)
    gemm_tc<0, false><<<gN2, 512>>>(h1h, h1l, whi + 1 * SEGSZ, wlo + 1 * SEGSZ,
        m2b1, nullptr, nullptr, nullptr, P, nullptr, nullptr, 512, nullptr, nullptr, nullptr);
    // 4: mlp2 fc2 edge GEMM with fused combine-load (PROFILED SLOT)
    gemm_tc<1, true><<<gE, 512>>>(nullptr, nullptr, whi + 3 * SEGSZ, wlo + 3 * SEGSZ,
        m2b2, nullptr, nullptr, nullptr, nullptr, e2h, e2l, 256, send, recv, P);
    // 5: edge2node
    edge2node<<<TN, 256>>>();
    // 6-7: mlp3
    gemm_tc<1, false><<<gN, 512>>>(nsh, nsl, whi + 4 * SEGSZ, wlo + 4 * SEGSZ,
        m3b1, nullptr, nullptr, nullptr, nullptr, nbh, nbl, 256, nullptr, nullptr, nullptr);
    gemm_tc<1, false><<<gN, 512>>>(nbh, nbl, whi + 5 * SEGSZ, wlo + 5 * SEGSZ,
        m3b2, nullptr, nullptr, nullptr, nullptr, n3h, n3l, 256, nullptr, nullptr, nullptr);
    // 8: mlp4 node products Q
    gemm_tc<0, false><<<gN2, 512>>>(n3h, n3l, whi + 6 * SEGSZ, wlo + 6 * SEGSZ,
        nullptr, nullptr, nullptr, nullptr, Q, nullptr, nullptr, 512, nullptr, nullptr, nullptr);
    // 9: mlp4 skip edge GEMM with gather epilogue
    gemm_tc<2, false><<<gE, 512>>>(e2h, e2l, whi + 8 * SEGSZ, wlo + 8 * SEGSZ,
        m4b1, nullptr, nullptr, nullptr, nullptr, tmph, tmpl, 256, send, recv, Q);
    // 10: mlp4 fc2
    gemm_tc<1, false><<<gE, 512>>>(tmph, tmpl, whi + 9 * SEGSZ, wlo + 9 * SEGSZ,
        m4b2, nullptr, nullptr, nullptr, nullptr, e4h, e4l, 256, nullptr, nullptr, nullptr);
    // 11: fused LSTM input projections -> g_g [TE][512]
    gemm_tc<3, false><<<gE2, 512>>>(e4h, e4l, whi + 10 * SEGSZ, wlo + 10 * SEGSZ,
        fbih, fbhh, rbih, rbhh, gg, nullptr, nullptr, 512, nullptr, nullptr, nullptr);
    // 12: recurrence
    lstm_kernel<<<2 * LSTM_BPD, 256, LSTM_SMEM>>>(gg, fWhh, rWhh, hfp, hrp);
    // 13: outputs
    out_proj<<<TE / 256, 256>>>(hfp, hrp, priW, prib, encW, encb, (float*)d_out);
}

// round 16
// speedup vs baseline: 1.1147x; 1.1147x over previous
#include <cuda_runtime.h>
#include <cuda_bf16.h>
#include <cstdint>

// ---------------- problem constants ----------------
constexpr int T_ = 64, N_ = 40, D_ = 4, H_ = 256, R_ = 64;
constexpr int E_ = N_ * (N_ - 1);        // 1560
constexpr int TE = T_ * E_;              // 99840
constexpr int TN = T_ * N_;              // 2560

// ---------------- scratch ----------------
__device__ __align__(16) __nv_bfloat16 g_nbh[TN * H_], g_nbl[TN * H_];
__device__ __align__(16) __nv_bfloat16 g_h1h[TN * H_], g_h1l[TN * H_];
__device__ __align__(16) __nv_bfloat16 g_nsh[TN * H_], g_nsl[TN * H_];
__device__ __align__(16) __nv_bfloat16 g_n3h[TN * H_], g_n3l[TN * H_];
__device__ __align__(16) __nv_bfloat16 g_tmph[TE * H_], g_tmpl[TE * H_];
__device__ __align__(16) __nv_bfloat16 g_e2h[TE * H_], g_e2l[TE * H_];
__device__ __align__(16) __nv_bfloat16 g_e4h[TE * H_], g_e4l[TE * H_];
__device__ __align__(16) float g_P[TN * 512];
__device__ __align__(16) float g_Q[TN * 512];
__device__ __align__(16) float g_g[(size_t)TE * 512];
constexpr int NSEG = 12;
constexpr int SEGSZ = 65536;
__device__ __align__(16) __nv_bfloat16 g_whi[NSEG * SEGSZ], g_wlo[NSEG * SEGSZ];
__device__ float g_hf[TE * R_];
__device__ float g_hr[TE * R_];
__device__ int   g_rlist[N_ * (N_ - 1)];

__device__ __forceinline__ float eluf(float v) { return v > 0.f ? v : expm1f(v); }
__device__ __forceinline__ float sigmf(float v) { return 1.f / (1.f + expf(-v)); }

__device__ __forceinline__ void bsplit2(float x0, float x1, uint32_t& hi, uint32_t& lo) {
    asm("cvt.rn.bf16x2.f32 %0, %1, %2;" : "=r"(hi) : "f"(x1), "f"(x0));
    __nv_bfloat162 h = *reinterpret_cast<__nv_bfloat162*>(&hi);
    float r0 = x0 - __bfloat162float(h.x);
    float r1 = x1 - __bfloat162float(h.y);
    asm("cvt.rn.bf16x2.f32 %0, %1, %2;" : "=r"(lo) : "f"(r1), "f"(r0));
}

__device__ __forceinline__ void mma_bf16(float* d, const uint32_t* a, uint32_t b0, uint32_t b1) {
    asm volatile(
        "mma.sync.aligned.m16n8k16.row.col.f32.bf16.bf16.f32 "
        "{%0,%1,%2,%3},{%4,%5,%6,%7},{%8,%9},{%0,%1,%2,%3};"
        : "+f"(d[0]), "+f"(d[1]), "+f"(d[2]), "+f"(d[3])
        : "r"(a[0]), "r"(a[1]), "r"(a[2]), "r"(a[3]), "r"(b0), "r"(b1));
}

__device__ __forceinline__ void ldsm4(uint32_t* r, uint32_t addr) {
    asm volatile("ldmatrix.sync.aligned.m8n8.x4.shared.b16 {%0,%1,%2,%3}, [%4];"
                 : "=r"(r[0]), "=r"(r[1]), "=r"(r[2]), "=r"(r[3]) : "r"(addr));
}

__device__ __forceinline__ uint32_t smem_u32(const void* p) {
    uint32_t a;
    asm("{ .reg .u64 t; cvta.to.shared.u64 t, %1; cvt.u32.u64 %0, t; }" : "=r"(a) : "l"(p));
    return a;
}

#define CP16(dst, src) \
    asm volatile("cp.async.cg.shared.global [%0], [%1], 16;" :: "r"(dst), "l"(src))
#define CPCOMMIT() asm volatile("cp.async.commit_group;")
#define CPWAIT2()  asm volatile("cp.async.wait_group 2;" ::: "memory")

// packed fp32x2 helpers
#define PACKF2(d, lo, hi) asm("mov.b64 %0, {%1, %2};" : "=l"(d) : "f"(lo), "f"(hi))
#define UNPACKF2(lo, hi, s) asm("mov.b64 {%0, %1}, %2;" : "=f"(lo), "=f"(hi) : "l"(s))
#define FMA2(d, a, b) asm("fma.rn.f32x2 %0, %1, %2, %0;" : "+l"(d) : "l"(a), "l"(b))

// ---------------- fused prep ----------------
struct SplitSeg { const float* src; int stride; int coff; };
struct SplitArgs { SplitSeg s[NSEG]; };
constexpr int PREP_SPLIT_BLKS = NSEG * 256;
constexpr int PREP_MLP1_BLKS = TN * H_ / 256;
constexpr int PREP_GRID = PREP_SPLIT_BLKS + PREP_MLP1_BLKS + 1;

__global__ void prep(SplitArgs a, __nv_bfloat16* __restrict__ oh,
                     __nv_bfloat16* __restrict__ ol,
                     const float* __restrict__ x, const float* __restrict__ W1,
                     const float* __restrict__ b1, const int* __restrict__ recv) {
    int id = blockIdx.x;
    int tid = threadIdx.x;
    if (id < PREP_SPLIT_BLKS) {
        int seg = id >> 8;
        int idx = (id & 255) * 256 + tid;
        int j = idx >> 8, k = idx & 255;
        const SplitSeg s = a.s[seg];
        float v = s.src[j * s.stride + s.coff + k];
        __nv_bfloat16 h = __float2bfloat16(v);
        int o = seg * SEGSZ + idx;
        oh[o] = h;
        ol[o] = __float2bfloat16(v - __bfloat162float(h));
    } else if (id < PREP_SPLIT_BLKS + PREP_MLP1_BLKS) {
        int idx = (id - PREP_SPLIT_BLKS) * 256 + tid;
        int row = idx >> 8;
        int j = idx & 255;
        const float* xr = x + row * D_;
        const float* w = W1 + j * D_;
        float v = b1[j] + xr[0] * w[0] + xr[1] * w[1] + xr[2] * w[2] + xr[3] * w[3];
        v = eluf(v);
        __nv_bfloat16 h = __float2bfloat16(v);
        g_nbh[idx] = h;
        g_nbl[idx] = __float2bfloat16(v - __bfloat162float(h));
    } else {
        int n = tid;
        if (n < N_) {
            int p = 0;
            for (int e = 0; e < E_; e++)
                if (recv[e] == n) g_rlist[n * (N_ - 1) + p++] = e;
        }
    }
}

// ---------------- edge2node scatter-add ----------------
__global__ void edge2node() {
    int b = blockIdx.x;
    int t = b / N_;
    int n = b - t * N_;
    int c = threadIdx.x;
    const int* lst = g_rlist + n * (N_ - 1);
    float s = 0.f;
#pragma unroll 13
    for (int i = 0; i < N_ - 1; i++) {
        int e = lst[i];
        size_t idx = ((size_t)t * E_ + e) * H_ + c;
        s += __bfloat162float(g_e2h[idx]) + __bfloat162float(g_e2l[idx]);
    }
    __nv_bfloat16 h = __float2bfloat16(s);
    g_nsh[(size_t)b * H_ + c] = h;
    g_nsl[(size_t)b * H_ + c] = __float2bfloat16(s - __bfloat162float(h));
}

// ------- bf16x3 tensor-core GEMM: 128x128 tiles, 3-stage cp.async pipeline -------
// CORRECT ordering: cp issue -> wait_group -> sts_a -> __syncthreads -> consume.
// Stage layout (24576 B): Ahi[0,6144) Alo[6144,12288) Bhi[12288,18432) Blo[18432,24576)
constexpr int STGB = 24576;
constexpr int GEMM_SMEM = 3 * STGB;   // 73728

template <int EPI, bool LOADP>
__global__ __launch_bounds__(256, 2) void gemm_tc(
    const __nv_bfloat16* __restrict__ Ah, const __nv_bfloat16* __restrict__ Al,
    const __nv_bfloat16* __restrict__ Wh, const __nv_bfloat16* __restrict__ Wl,
    const float* __restrict__ b0p, const float* __restrict__ b1p,
    const float* __restrict__ b2p, const float* __restrict__ b3p,
    float* __restrict__ Cf, __nv_bfloat16* __restrict__ Ch, __nv_bfloat16* __restrict__ Cl,
    int ldc,
    const int* __restrict__ send, const int* __restrict__ recv,
    const float* __restrict__ Q) {
    extern __shared__ __align__(16) char smem[];
    const uint32_t sb = smem_u32(smem);
    const int tid = threadIdx.x;
    const int bm = blockIdx.y * 128;
    const int bn = blockIdx.x * 128;
    const int warp = tid >> 5, lane = tid & 31;

    const int row = tid >> 1;
    const int half = tid & 1;
    const __nv_bfloat16* arh = Ah + (size_t)(bm + row) * H_ + half * 8;
    const __nv_bfloat16* arl = Al + (size_t)(bm + row) * H_ + half * 8;
    const float *p0 = nullptr, *p1 = nullptr;
    if (LOADP) {
        int m = bm + row;
        int t = m / E_;
        int e = m - t * E_;
        p0 = Q + ((size_t)t * N_ + send[e]) * 512 + half * 8;
        p1 = Q + ((size_t)t * N_ + recv[e]) * 512 + 256 + half * 8;
    }
    const __nv_bfloat16* wrh = Wh + (size_t)(bn + row) * H_ + half * 8;
    const __nv_bfloat16* wrl = Wl + (size_t)(bn + row) * H_ + half * 8;
    const uint32_t lane_off = (uint32_t)(row * 48 + half * 16);

    const int wm = (warp >> 2) * 64, wn = (warp & 3) * 32;
    const int lrow = lane & 15, lkh = lane >> 4;
    const uint32_t a_off = (uint32_t)((wm + lrow) * 48 + lkh * 16);
    const uint32_t b_off = 12288u + (uint32_t)((wn + lrow) * 48 + lkh * 16);

    float acc[4][4][4] = {};

    uint4 vah, vaL;
    auto load_a = [&](int s) {
        int kt = s * 16;
        if (LOADP) {
            float4 x0 = *(const float4*)(p0 + kt);
            float4 x1 = *(const float4*)(p0 + kt + 4);
            float4 y0 = *(const float4*)(p1 + kt);
            float4 y1 = *(const float4*)(p1 + kt + 4);
            float v0 = eluf(x0.x + y0.x), v1 = eluf(x0.y + y0.y);
            float v2 = eluf(x0.z + y0.z), v3 = eluf(x0.w + y0.w);
            float v4 = eluf(x1.x + y1.x), v5 = eluf(x1.y + y1.y);
            float v6 = eluf(x1.z + y1.z), v7 = eluf(x1.w + y1.w);
            bsplit2(v0, v1, vah.x, vaL.x);
            bsplit2(v2, v3, vah.y, vaL.y);
            bsplit2(v4, v5, vah.z, vaL.z);
            bsplit2(v6, v7, vah.w, vaL.w);
        } else {
            vah = *(const uint4*)(arh + kt);
            vaL = *(const uint4*)(arl + kt);
        }
    };
    auto sts_a = [&](int s) {
        char* d = smem + (s % 3) * STGB + lane_off;
        *(uint4*)(d + 0)    = vah;
        *(uint4*)(d + 6144) = vaL;
    };
    auto cp_b = [&](int s) {
        uint32_t d = sb + (uint32_t)((s % 3) * STGB) + 12288u + lane_off;
        CP16(d, wrh + s * 16);
        CP16(d + 6144, wrl + s * 16);
    };

    // prologue: A stage0 stored, A stage1 in regs; B stages 0,1 in flight
    load_a(0);
    sts_a(0);
    load_a(1);
    cp_b(0); CPCOMMIT();
    cp_b(1); CPCOMMIT();

#pragma unroll 1
    for (int j = 0; j < 16; j++) {
        if (j + 2 < 16) cp_b(j + 2);
        CPCOMMIT();
        CPWAIT2();                    // this thread's B(j) copies retired
        if (j + 1 < 16) {
            sts_a(j + 1);
            if (j + 2 < 16) load_a(j + 2);
        }
        __syncthreads();              // publish B(j) from ALL threads + A(j) stores

        const uint32_t st = sb + (uint32_t)((j % 3) * STGB);
        uint32_t ah[4][4], al[4][4], bh[2][4], bl[2][4];
#pragma unroll
        for (int mf = 0; mf < 4; mf++) {
            ldsm4(ah[mf], st + a_off + mf * 768u);
            ldsm4(al[mf], st + a_off + mf * 768u + 6144u);
        }
#pragma unroll
        for (int p = 0; p < 2; p++) {
            ldsm4(bh[p], st + b_off + p * 768u);
            ldsm4(bl[p], st + b_off + p * 768u + 6144u);
        }
#pragma unroll
        for (int nf = 0; nf < 4; nf++) {
            const int p = nf >> 1, o = nf & 1;
#pragma unroll
            for (int mf = 0; mf < 4; mf++)
                mma_bf16(acc[mf][nf], ah[mf], bh[p][o], bh[p][o + 2]);
        }
#pragma unroll
        for (int nf = 0; nf < 4; nf++) {
            const int p = nf >> 1, o = nf & 1;
#pragma unroll
            for (int mf = 0; mf < 4; mf++)
                mma_bf16(acc[mf][nf], ah[mf], bl[p][o], bl[p][o + 2]);
        }
#pragma unroll
        for (int nf = 0; nf < 4; nf++) {
            const int p = nf >> 1, o = nf & 1;
#pragma unroll
            for (int mf = 0; mf < 4; mf++)
                mma_bf16(acc[mf][nf], al[mf], bh[p][o], bh[p][o + 2]);
        }
    }

    // ---- epilogue ----
    const int grp = lane >> 2, q = lane & 3;
#pragma unroll
    for (int mf = 0; mf < 4; mf++) {
        int r0 = bm + wm + mf * 16 + grp;
        int r1 = r0 + 8;
        size_t qs0 = 0, qr0 = 0, qs1 = 0, qr1 = 0;
        if (EPI == 2) {
            int t0 = r0 / E_, e0 = r0 - t0 * E_;
            int t1 = r1 / E_, e1 = r1 - t1 * E_;
            qs0 = ((size_t)t0 * N_ + send[e0]) * 512;
            qr0 = ((size_t)t0 * N_ + recv[e0]) * 512 + 256;
            qs1 = ((size_t)t1 * N_ + send[e1]) * 512;
            qr1 = ((size_t)t1 * N_ + recv[e1]) * 512 + 256;
        }
#pragma unroll
        for (int nf = 0; nf < 4; nf++) {
            int col = wn + nf * 8 + 2 * q;
            int cg = bn + col;
            float b0 = 0.f, b1 = 0.f;
            if (EPI == 1 || EPI == 2) { b0 = b0p[cg]; b1 = b0p[cg + 1]; }
            if (EPI == 0 && b0p != nullptr && cg < 256) { b0 = b0p[cg]; b1 = b0p[cg + 1]; }
            if (EPI == 3) {
                if (cg < 256) { b0 = b0p[cg] + b1p[cg]; b1 = b0p[cg + 1] + b1p[cg + 1]; }
                else { b0 = b2p[cg - 256] + b3p[cg - 256]; b1 = b2p[cg - 255] + b3p[cg - 255]; }
            }
            float x0 = acc[mf][nf][0] + b0;
            float x1 = acc[mf][nf][1] + b1;
            float x2 = acc[mf][nf][2] + b0;
            float x3 = acc[mf][nf][3] + b1;
            if (EPI == 2) {
                x0 += Q[qs0 + cg] + Q[qr0 + cg];
                x1 += Q[qs0 + cg + 1] + Q[qr0 + cg + 1];
                x2 += Q[qs1 + cg] + Q[qr1 + cg];
                x3 += Q[qs1 + cg + 1] + Q[qr1 + cg + 1];
            }
            if (EPI == 1 || EPI == 2) {
                x0 = eluf(x0); x1 = eluf(x1); x2 = eluf(x2); x3 = eluf(x3);
                uint32_t h01, l01, h23, l23;
                bsplit2(x0, x1, h01, l01);
                bsplit2(x2, x3, h23, l23);
                *(uint32_t*)(Ch + (size_t)r0 * 256 + cg) = h01;
                *(uint32_t*)(Cl + (size_t)r0 * 256 + cg) = l01;
                *(uint32_t*)(Ch + (size_t)r1 * 256 + cg) = h23;
                *(uint32_t*)(Cl + (size_t)r1 * 256 + cg) = l23;
            } else {
                *(float2*)(Cf + (size_t)r0 * ldc + cg) = make_float2(x0, x1);
                *(float2*)(Cf + (size_t)r1 * ldc + cg) = make_float2(x2, x3);
            }
        }
    }
}

// ---- bidirectional LSTM (unchanged) ----
constexpr int LSTM_GROUPS = E_ / 8;
constexpr int LSTM_GPB = 4;
constexpr int LSTM_BPD = (LSTM_GROUPS + LSTM_GPB - 1) / LSTM_GPB;
constexpr int LSTM_SMEM = 64 * 256 * 4 + LSTM_GPB * 64 * 8 * 4;

__global__ __launch_bounds__(256) void lstm_kernel(
    const float* __restrict__ gates,
    const float* __restrict__ fWhh, const float* __restrict__ rWhh,
    float* __restrict__ hfOut, float* __restrict__ hrOut) {
    extern __shared__ float sm[];
    float* Wq = sm;
    float4* hsm = (float4*)(sm + 64 * 256);

    const int bid = blockIdx.x;
    const int dir = (bid >= LSTM_BPD) ? 1 : 0;
    const int bg = dir ? (bid - LSTM_BPD) : bid;
    const float* Whh = dir ? rWhh : fWhh;
    float* hout = dir ? hrOut : hfOut;
    const int doff = dir * 256;
    const int tid = threadIdx.x;
    const int sub = tid >> 6, j = tid & 63;
    const int grp = bg * LSTM_GPB + sub;
    const bool valid = grp < LSTM_GROUPS;
    const int e0 = (valid ? grp : LSTM_GROUPS - 1) * 8;

    for (int idx = tid; idx < 64 * 256; idx += 256) {
        int k = idx >> 8;
        int rem = idx & 255;
        int jj = rem >> 2;
        int q = rem & 3;
        Wq[idx] = Whh[(q * 64 + jj) * 64 + k];
    }
    float4* hme = hsm + sub * 128;
    for (int i = j; i < 128; i += 64) hme[i] = make_float4(0.f, 0.f, 0.f, 0.f);

    float c[8];
#pragma unroll
    for (int e = 0; e < 8; e++) c[e] = 0.f;
    __syncthreads();

    for (int s = 0; s < T_; s++) {
        int t = dir ? (T_ - 1 - s) : s;
        unsigned long long A0[4], A1[4], A2[4], A3[4];
        {
            float a0[8], a1[8], a2[8], a3[8];
#pragma unroll
            for (int e = 0; e < 8; e++) {
                const float* gp = gates + ((size_t)t * E_ + e0 + e) * 512 + doff;
                a0[e] = gp[j]; a1[e] = gp[64 + j]; a2[e] = gp[128 + j]; a3[e] = gp[192 + j];
            }
#pragma unroll
            for (int p = 0; p < 4; p++) {
                PACKF2(A0[p], a0[2 * p], a0[2 * p + 1]);
                PACKF2(A1[p], a1[2 * p], a1[2 * p + 1]);
                PACKF2(A2[p], a2[2 * p], a2[2 * p + 1]);
                PACKF2(A3[p], a3[2 * p], a3[2 * p + 1]);
            }
        }
#pragma unroll 8
        for (int k = 0; k < 64; k++) {
            float4 w = *(const float4*)&Wq[k * 256 + j * 4];
            unsigned long long wx, wy, wz, ww;
            PACKF2(wx, w.x, w.x);
            PACKF2(wy, w.y, w.y);
            PACKF2(wz, w.z, w.z);
            PACKF2(ww, w.w, w.w);
            const ulonglong2* hp = (const ulonglong2*)(hme + k * 2);
            ulonglong2 hA = hp[0], hB = hp[1];
            unsigned long long hv[4] = {hA.x, hA.y, hB.x, hB.y};
#pragma unroll
            for (int p = 0; p < 4; p++) {
                FMA2(A0[p], hv[p], wx);
                FMA2(A1[p], hv[p], wy);
                FMA2(A2[p], hv[p], wz);
                FMA2(A3[p], hv[p], ww);
            }
        }
        __syncthreads();
        float a0[8], a1[8], a2[8], a3[8];
#pragma unroll
        for (int p = 0; p < 4; p++) {
            UNPACKF2(a0[2 * p], a0[2 * p + 1], A0[p]);
            UNPACKF2(a1[2 * p], a1[2 * p + 1], A1[p]);
            UNPACKF2(a2[2 * p], a2[2 * p + 1], A2[p]);
            UNPACKF2(a3[2 * p], a3[2 * p + 1], A3[p]);
        }
        float hn[8];
#pragma unroll
        for (int e = 0; e < 8; e++) {
            float iv = sigmf(a0[e]);
            float fv = sigmf(a1[e]);
            float gv = tanhf(a2[e]);
            float ov = sigmf(a3[e]);
            c[e] = fv * c[e] + iv * gv;
            hn[e] = ov * tanhf(c[e]);
        }
        hme[j * 2 + 0] = make_float4(hn[0], hn[1], hn[2], hn[3]);
        hme[j * 2 + 1] = make_float4(hn[4], hn[5], hn[6], hn[7]);
        if (valid) {
#pragma unroll
            for (int e = 0; e < 8; e++)
                hout[((size_t)t * E_ + e0 + e) * 64 + j] = hn[e];
        }
        __syncthreads();
    }
}

// ---------------- output projection ----------------
__global__ void out_proj(const float* __restrict__ hf, const float* __restrict__ hr,
                         const float* __restrict__ priW, const float* __restrict__ prib,
                         const float* __restrict__ encW, const float* __restrict__ encb,
                         float* __restrict__ out) {
    int m = blockIdx.x * blockDim.x + threadIdx.x;
    if (m >= TE) return;
    const float* f = hf + (size_t)m * 64;
    const float* r = hr + (size_t)m * 64;
    float p0 = prib[0], p1 = prib[1], e0 = encb[0], e1 = encb[1];
#pragma unroll 8
    for (int k = 0; k < 64; k++) {
        float fv = f[k];
        p0 = fmaf(fv, priW[k], p0);
        p1 = fmaf(fv, priW[64 + k], p1);
        e0 = fmaf(fv, encW[k], e0);
        e1 = fmaf(fv, encW[128 + k], e1);
    }
#pragma unroll 8
    for (int k = 0; k < 64; k++) {
        float rv = r[k];
        e0 = fmaf(rv, encW[64 + k], e0);
        e1 = fmaf(rv, encW[192 + k], e1);
    }
    float4 o = make_float4(p0, p1, e0, e1);
    *(float4*)(out + (size_t)m * 4) = o;
}

// ---------------- host launch ----------------
extern "C" void kernel_launch(void* const* d_in, const int* in_sizes, int n_in,
                              void* d_out, int out_size) {
    const float* x     = (const float*)d_in[0];
    const int* send    = (const int*)d_in[2];
    const int* recv    = (const int*)d_in[3];
    const float* m1W1 = (const float*)d_in[4],  *m1b1 = (const float*)d_in[5];
    const float* m1W2 = (const float*)d_in[6],  *m1b2 = (const float*)d_in[7];
    const float* m2W1 = (const float*)d_in[8],  *m2b1 = (const float*)d_in[9];
    const float* m2W2 = (const float*)d_in[10], *m2b2 = (const float*)d_in[11];
    const float* m3W1 = (const float*)d_in[12], *m3b1 = (const float*)d_in[13];
    const float* m3W2 = (const float*)d_in[14], *m3b2 = (const float*)d_in[15];
    const float* m4W1 = (const float*)d_in[16], *m4b1 = (const float*)d_in[17];
    const float* m4W2 = (const float*)d_in[18], *m4b2 = (const float*)d_in[19];
    const float* fWih = (const float*)d_in[20], *fWhh = (const float*)d_in[21];
    const float* fbih = (const float*)d_in[22], *fbhh = (const float*)d_in[23];
    const float* rWih = (const float*)d_in[24], *rWhh = (const float*)d_in[25];
    const float* rbih = (const float*)d_in[26], *rbhh = (const float*)d_in[27];
    const float* encW = (const float*)d_in[28], *encb = (const float*)d_in[29];
    const float* priW = (const float*)d_in[30], *prib = (const float*)d_in[31];

    __nv_bfloat16 *whi, *wlo, *nbh, *nbl, *h1h, *h1l, *nsh, *nsl, *n3h, *n3l;
    __nv_bfloat16 *tmph, *tmpl, *e2h, *e2l, *e4h, *e4l;
    float *P, *Q, *gg, *hfp, *hrp;
    cudaGetSymbolAddress((void**)&whi,  g_whi);
    cudaGetSymbolAddress((void**)&wlo,  g_wlo);
    cudaGetSymbolAddress((void**)&nbh,  g_nbh);
    cudaGetSymbolAddress((void**)&nbl,  g_nbl);
    cudaGetSymbolAddress((void**)&h1h,  g_h1h);
    cudaGetSymbolAddress((void**)&h1l,  g_h1l);
    cudaGetSymbolAddress((void**)&nsh,  g_nsh);
    cudaGetSymbolAddress((void**)&nsl,  g_nsl);
    cudaGetSymbolAddress((void**)&n3h,  g_n3h);
    cudaGetSymbolAddress((void**)&n3l,  g_n3l);
    cudaGetSymbolAddress((void**)&tmph, g_tmph);
    cudaGetSymbolAddress((void**)&tmpl, g_tmpl);
    cudaGetSymbolAddress((void**)&e2h,  g_e2h);
    cudaGetSymbolAddress((void**)&e2l,  g_e2l);
    cudaGetSymbolAddress((void**)&e4h,  g_e4h);
    cudaGetSymbolAddress((void**)&e4l,  g_e4l);
    cudaGetSymbolAddress((void**)&P,    g_P);
    cudaGetSymbolAddress((void**)&Q,    g_Q);
    cudaGetSymbolAddress((void**)&gg,   g_g);
    cudaGetSymbolAddress((void**)&hfp,  g_hf);
    cudaGetSymbolAddress((void**)&hrp,  g_hr);

    cudaFuncSetAttribute(lstm_kernel, cudaFuncAttributeMaxDynamicSharedMemorySize, LSTM_SMEM);
    cudaFuncSetAttribute(gemm_tc<0, false>, cudaFuncAttributeMaxDynamicSharedMemorySize, GEMM_SMEM);
    cudaFuncSetAttribute(gemm_tc<1, false>, cudaFuncAttributeMaxDynamicSharedMemorySize, GEMM_SMEM);
    cudaFuncSetAttribute(gemm_tc<1, true>,  cudaFuncAttributeMaxDynamicSharedMemorySize, GEMM_SMEM);
    cudaFuncSetAttribute(gemm_tc<2, false>, cudaFuncAttributeMaxDynamicSharedMemorySize, GEMM_SMEM);
    cudaFuncSetAttribute(gemm_tc<3, false>, cudaFuncAttributeMaxDynamicSharedMemorySize, GEMM_SMEM);

    SplitArgs sa;
    sa.s[0]  = {m1W2, 256, 0};
    sa.s[1]  = {m2W1, 512, 0};
    sa.s[2]  = {m2W1, 512, 256};
    sa.s[3]  = {m2W2, 256, 0};
    sa.s[4]  = {m3W1, 256, 0};
    sa.s[5]  = {m3W2, 256, 0};
    sa.s[6]  = {m4W1, 768, 0};
    sa.s[7]  = {m4W1, 768, 256};
    sa.s[8]  = {m4W1, 768, 512};
    sa.s[9]  = {m4W2, 256, 0};
    sa.s[10] = {fWih, 256, 0};
    sa.s[11] = {rWih, 256, 0};

    const dim3 gN(2, TN / 128);
    const dim3 gN2(4, TN / 128);
    const dim3 gE(2, TE / 128);
    const dim3 gE2(4, TE / 128);

    // 1: prep
    prep<<<PREP_GRID, 256>>>(sa, whi, wlo, x, m1W1, m1b1, recv);
    // 2: mlp1 fc2 (node)
    gemm_tc<1, false><<<gN, 256, GEMM_SMEM>>>(nbh, nbl, whi + 0 * SEGSZ, wlo + 0 * SEGSZ,
        m1b2, nullptr, nullptr, nullptr, nullptr, h1h, h1l, 256, nullptr, nullptr, nullptr);
    // 3: mlp2 fc1 node products P = h1 @ [Ws|Wr]  (+ m2b1 on first half)
    gemm_tc<0, false><<<gN2, 256, GEMM_SMEM>>>(h1h, h1l, whi + 1 * SEGSZ, wlo + 1 * SEGSZ,
        m2b1, nullptr, nullptr, nullptr, P, nullptr, nullptr, 512, nullptr, nullptr, nullptr);
    // 4: mlp2 fc2 edge GEMM with fused combine-load (PROFILED SLOT)
    gemm_tc<1, true><<<gE, 256, GEMM_SMEM>>>(nullptr, nullptr, whi + 3 * SEGSZ, wlo + 3 * SEGSZ,
        m2b2, nullptr, nullptr, nullptr, nullptr, e2h, e2l, 256, send, recv, P);
    // 5: edge2node
    edge2node<<<TN, 256>>>();
    // 6-7: mlp3
    gemm_tc<1, false><<<gN, 256, GEMM_SMEM>>>(nsh, nsl, whi + 4 * SEGSZ, wlo + 4 * SEGSZ,
        m3b1, nullptr, nullptr, nullptr, nullptr, nbh, nbl, 256, nullptr, nullptr, nullptr);
    gemm_tc<1, false><<<gN, 256, GEMM_SMEM>>>(nbh, nbl, whi + 5 * SEGSZ, wlo + 5 * SEGSZ,
        m3b2, nullptr, nullptr, nullptr, nullptr, n3h, n3l, 256, nullptr, nullptr, nullptr);
    // 8: mlp4 node products Q
    gemm_tc<0, false><<<gN2, 256, GEMM_SMEM>>>(n3h, n3l, whi + 6 * SEGSZ, wlo + 6 * SEGSZ,
        nullptr, nullptr, nullptr, nullptr, Q, nullptr, nullptr, 512, nullptr, nullptr, nullptr);
    // 9: mlp4 skip edge GEMM with gather epilogue
    gemm_tc<2, false><<<gE, 256, GEMM_SMEM>>>(e2h, e2l, whi + 8 * SEGSZ, wlo + 8 * SEGSZ,
        m4b1, nullptr, nullptr, nullptr, nullptr, tmph, tmpl, 256, send, recv, Q);
    // 10: mlp4 fc2
    gemm_tc<1, false><<<gE, 256, GEMM_SMEM>>>(tmph, tmpl, whi + 9 * SEGSZ, wlo + 9 * SEGSZ,
        m4b2, nullptr, nullptr, nullptr, nullptr, e4h, e4l, 256, nullptr, nullptr, nullptr);
    // 11: fused LSTM input projections -> g_g [TE][512]
    gemm_tc<3, false><<<gE2, 256, GEMM_SMEM>>>(e4h, e4l, whi + 10 * SEGSZ, wlo + 10 * SEGSZ,
        fbih, fbhh, rbih, rbhh, gg, nullptr, nullptr, 512, nullptr, nullptr, nullptr);
    // 12: recurrence
    lstm_kernel<<<2 * LSTM_BPD, 256, LSTM_SMEM>>>(gg, fWhh, rWhh, hfp, hrp);
    // 13: outputs
    out_proj<<<TE / 256, 256>>>(hfp, hrp, priW, prib, encW, encb, (float*)d_out);
}